// round 15
// baseline (speedup 1.0000x reference)
#include <cuda_runtime.h>

#define NA 100000
#define NP 3200000
#define FA 75
#define FPR 14
#define HH 50
#define FO 50
#define XS 52
typedef unsigned long long ull;

__device__ float g_AA[NA * HH];
__device__ float g_X1[NA * XS];
__device__ float g_X2[NA * XS];
__device__ float g_PA[NA * HH];

__device__ __forceinline__ float relu_(float x) { return fmaxf(x, 0.0f); }
__device__ __forceinline__ void fma2_(ull& d, ull a, ull b) {
    asm("fma.rn.f32x2 %0, %1, %2, %0;" : "+l"(d) : "l"(a), "l"(b));
}
__device__ __forceinline__ ull dup_(float x) {
    ull r; asm("mov.b64 %0, {%1, %1};" : "=l"(r) : "f"(x)); return r;
}
__device__ __forceinline__ float2 unpk_(ull v) {
    float2 f; asm("mov.b64 {%0, %1}, %2;" : "=f"(f.x), "=f"(f.y) : "l"(v)); return f;
}

// ============ K1: atom precompute (proven) ============
__global__ __launch_bounds__(256) void atom_pre_kernel(
    const float* __restrict__ af, const float* __restrict__ W_AA,
    const float* __restrict__ b_AA, const float* __restrict__ W_AP)
{
    __shared__ __align__(16) float AsT[76 * 68];
    __shared__ __align__(16) float BsT[76 * 68];
    __shared__ float bsh[64];
    const int abase = blockIdx.x * 64;
    const int tid = threadIdx.x;

    for (int idx = tid; idx < 64 * 76; idx += 256) {
        int k = idx % 76, m = idx / 76;
        int a = abase + m;
        AsT[k * 68 + m] = (k < FA && a < NA) ? af[a * FA + k] : 0.0f;
    }
    for (int idx = tid; idx < 64 * HH; idx += 256) {
        int m = idx / HH, o = idx % HH;
        int a = abase + m;
        if (a < NA) g_PA[a * HH + o] = 0.0f;
    }
    for (int idx = tid; idx < 64 * 2; idx += 256) {
        int m = idx >> 1, o = 50 + (idx & 1);
        int a = abase + m;
        if (a < NA) { g_X1[(size_t)a * XS + o] = 0.0f; g_X2[(size_t)a * XS + o] = 0.0f; }
    }
    if (tid < 64) bsh[tid] = (tid < HH) ? b_AA[tid] : 0.0f;

    const int tm = tid >> 4, tn = tid & 15;
    const int m0 = tm * 4, n0 = tn * 4;

    for (int mat = 0; mat < 3; mat++) {
        __syncthreads();
        const float* W; int ws, wo;
        if (mat == 0) { W = W_AA; ws = FA;     wo = 0; }
        else          { W = W_AP; ws = 2 * FA; wo = (mat == 1) ? 0 : FA; }
        for (int idx = tid; idx < 64 * 76; idx += 256) {
            int k = idx % 76, o = idx / 76;
            BsT[k * 68 + o] = (k < FA && o < HH) ? W[o * ws + wo + k] : 0.0f;
        }
        __syncthreads();
        ull acc2[2][4];
#pragma unroll
        for (int rp = 0; rp < 2; rp++)
#pragma unroll
            for (int c = 0; c < 4; c++) acc2[rp][c] = 0ull;
#pragma unroll 5
        for (int k = 0; k < 75; k++) {
            ulonglong2 a2 = *(const ulonglong2*)&AsT[k * 68 + m0];
            float4 b4 = *(const float4*)&BsT[k * 68 + n0];
            ull av[2] = {a2.x, a2.y};
            ull bd[4] = {dup_(b4.x), dup_(b4.y), dup_(b4.z), dup_(b4.w)};
#pragma unroll
            for (int rp = 0; rp < 2; rp++)
#pragma unroll
                for (int c = 0; c < 4; c++) fma2_(acc2[rp][c], av[rp], bd[c]);
        }
        float* dst = (mat == 0) ? g_AA : ((mat == 1) ? g_X1 : g_X2);
        const int ds = (mat == 0) ? HH : XS;
#pragma unroll
        for (int rp = 0; rp < 2; rp++)
#pragma unroll
            for (int c = 0; c < 4; c++) {
                int o = n0 + c;
                if (o < HH) {
                    float2 f2 = unpk_(acc2[rp][c]);
                    int a0 = abase + m0 + 2 * rp;
                    if (mat == 0) { f2.x = relu_(f2.x + bsh[o]); f2.y = relu_(f2.y + bsh[o]); }
                    if (a0 < NA)     dst[(size_t)a0 * ds + o]       = f2.x;
                    if (a0 + 1 < NA) dst[(size_t)(a0 + 1) * ds + o] = f2.y;
                }
            }
    }
}

// ============ K2: persistent pair kernel (R13 structure + pre-dup'd Wpa/Wpp, WT stride 52) ============
#define NT (NP / 64)
#define GRID_P 444
// floats: CT 6800 | WT 100*52=5200 | pfT 16*68=1088 | WpaD 16*52 ull = 1664 fl |
//         WppD 1664 | biases 4*52 | sidx 128 | spsv 68 | sbal 2  => 16822
#define PAIR_SMEM_BYTES (16822 * 4)

__global__ __launch_bounds__(256, 3) void pair_kernel(
    const float* __restrict__ pf, const int* __restrict__ split,
    const int* __restrict__ atp,
    const float* __restrict__ W_PA, const float* __restrict__ b_PA,
    const float* __restrict__ W_PP, const float* __restrict__ b_PP,
    const float* __restrict__ W_P,  const float* __restrict__ b_P,
    const float* __restrict__ b_AP, float* __restrict__ outP)
{
    extern __shared__ __align__(16) float sm[];
    float* CT   = sm;                    // [100][68]
    float* WT   = CT + 6800;             // [100][52]  (row-remapped W_P^T: PP rows 0..49, S rows 50..99)
    float* pfT  = WT + 5200;             // [16][68]
    ull*  WpaD  = (ull*)(pfT + 1088);    // [16][52] dup'd pairs
    ull*  WppD  = WpaD + 16 * 52;        // [16][52]
    float* sbAP = (float*)(WppD + 16 * 52);  // 52
    float* sbPP = sbAP + 52;
    float* sbPA = sbPP + 52;
    float* sbP  = sbPA + 52;
    int* sidx   = (int*)(sbP + 52);      // 128
    int* spsv   = sidx + 128;            // 68
    int* sbal   = spsv + 68;             // 2

    const int tid = threadIdx.x;
    const int tm = tid >> 4, tn = tid & 15;
    const int m0 = tm * 4, n0 = tn * 4;

    // one-time weight staging
    for (int idx = tid; idx < 5200; idx += 256) {
        int r = idx % 100, o = idx / 100;       // o in 0..51
        int kk = (r < 50) ? (r + 50) : (r - 50);
        WT[r * 52 + o] = (o < FO) ? W_P[o * 2 * HH + kk] : 0.0f;
    }
    for (int idx = tid; idx < 16 * 52; idx += 256) {
        int k = idx % 16, o = idx / 16;
        bool v = (k < FPR && o < HH);
        WpaD[k * 52 + o] = dup_(v ? W_PA[o * FPR + k] : 0.0f);
        WppD[k * 52 + o] = dup_(v ? W_PP[o * FPR + k] : 0.0f);
    }
    if (tid < 52) {
        sbAP[tid] = (tid < HH) ? b_AP[tid] : 0.0f;
        sbPP[tid] = (tid < HH) ? b_PP[tid] : 0.0f;
        sbPA[tid] = (tid < HH) ? b_PA[tid] : 0.0f;
        sbP[tid]  = (tid < FO) ? b_P[tid]  : 0.0f;
    }
    {
        int t0 = blockIdx.x;
        if (t0 < NT) {
            int p0 = t0 * 64;
            for (int idx = tid; idx < 1024; idx += 256) {
                int kk = idx & 15, p = idx >> 4;
                pfT[kk * 68 + p] = (kk < FPR) ? __ldcs(&pf[(size_t)(p0 + p) * FPR + kk]) : 0.0f;
            }
            if (tid < 128) sidx[tid] = atp[(size_t)p0 * 2 + tid];
            if (tid < 65)  spsv[tid] = (tid == 0) ? -1 : split[p0 + tid - 1];
        }
    }
    __syncthreads();

    for (int t = blockIdx.x; t < NT; t += GRID_P) {
        const int p0 = t * 64;

        // ===== Phase A: ballot + S gathers -> rows 50..99 + P1 -> rows 0..49 =====
        if (tid < 64) {
            bool ish = (spsv[tid + 1] != spsv[tid]);
            unsigned bm = __ballot_sync(0xffffffffu, ish);
            if ((tid & 31) == 0) sbal[tid >> 5] = (int)bm;
        }
        for (int idx = tid; idx < 64 * 13; idx += 256) {
            int p = idx / 13, c = idx % 13;
            int k0 = c * 4;
            int i = sidx[2 * p], j = sidx[2 * p + 1];
            float4 a = *(const float4*)(g_X1 + (size_t)i * XS + k0);
            float4 b = *(const float4*)(g_X2 + (size_t)j * XS + k0);
            float4 d = *(const float4*)(g_X1 + (size_t)j * XS + k0);
            float4 e = *(const float4*)(g_X2 + (size_t)i * XS + k0);
            float4 bi = *(const float4*)(sbAP + k0);
            CT[(50 + k0 + 0) * 68 + p] = relu_(a.x + b.x + bi.x) + relu_(d.x + e.x + bi.x);
            CT[(50 + k0 + 1) * 68 + p] = relu_(a.y + b.y + bi.y) + relu_(d.y + e.y + bi.y);
            if (c < 12) {
                CT[(50 + k0 + 2) * 68 + p] = relu_(a.z + b.z + bi.z) + relu_(d.z + e.z + bi.z);
                CT[(50 + k0 + 3) * 68 + p] = relu_(a.w + b.w + bi.w) + relu_(d.w + e.w + bi.w);
            }
        }
        {   // P1: PA -> rows 0..49 (pre-dup'd B: no MOVs)
            ull acc2[2][4];
#pragma unroll
            for (int rp = 0; rp < 2; rp++)
#pragma unroll
                for (int c = 0; c < 4; c++) acc2[rp][c] = 0ull;
#pragma unroll
            for (int k = 0; k < FPR; k++) {
                ulonglong2 b01 = *(const ulonglong2*)&WpaD[k * 52 + n0];
                ulonglong2 b23 = *(const ulonglong2*)&WpaD[k * 52 + n0 + 2];
                ulonglong2 a2 = *(const ulonglong2*)&pfT[k * 68 + m0];
                ull av[2] = {a2.x, a2.y};
                ull bd[4] = {b01.x, b01.y, b23.x, b23.y};
#pragma unroll
                for (int rp = 0; rp < 2; rp++)
#pragma unroll
                    for (int c = 0; c < 4; c++) fma2_(acc2[rp][c], av[rp], bd[c]);
            }
#pragma unroll
            for (int c = 0; c < 4; c++) {
                int o = n0 + c;
                if (o < HH) {
                    float b = sbPA[o];
#pragma unroll
                    for (int rp = 0; rp < 2; rp++) {
                        float2 f2 = unpk_(acc2[rp][c]);
                        *(float2*)&CT[o * 68 + m0 + 2 * rp] =
                            make_float2(relu_(f2.x + b), relu_(f2.y + b));
                    }
                }
            }
        }
        __syncthreads();

        // ===== Phase B: ballot segsum + PP -> regs =====
        ull ppacc[2][4];
#pragma unroll
        for (int rp = 0; rp < 2; rp++)
#pragma unroll
            for (int c = 0; c < 4; c++) ppacc[rp][c] = 0ull;
        {
            ull mask = (ull)(unsigned)sbal[0] | ((ull)(unsigned)sbal[1] << 32);
            int nh = __popcll(mask);
            for (int w = tid; w < nh * 64; w += 256) {
                int o = w & 63, hi = w >> 6;
                if (o < HH) {
                    ull mm = mask;
                    for (int it = 0; it < hi; it++) mm &= mm - 1;
                    int h = __ffsll((long long)mm) - 1;
                    int e;
                    if (h >= 63) e = 64;
                    else {
                        ull rest = mask >> (h + 1);
                        e = rest ? (h + 1 + __ffsll((long long)rest) - 1) : 64;
                    }
                    int seg = spsv[h + 1];
                    const float* cr = &CT[o * 68];
                    float s = 0.0f;
                    int q = h;
                    int e4 = h + ((e - h) & ~3);
                    for (; q < e4; q += 4)
                        s += (cr[q] + cr[q + 1]) + (cr[q + 2] + cr[q + 3]);
                    for (; q < e; q++) s += cr[q];
                    atomicAdd(&g_PA[(size_t)seg * HH + o], s);
                }
            }
        }
#pragma unroll
        for (int k = 0; k < FPR; k++) {
            ulonglong2 b01 = *(const ulonglong2*)&WppD[k * 52 + n0];
            ulonglong2 b23 = *(const ulonglong2*)&WppD[k * 52 + n0 + 2];
            ulonglong2 a2 = *(const ulonglong2*)&pfT[k * 68 + m0];
            ull av[2] = {a2.x, a2.y};
            ull bd[4] = {b01.x, b01.y, b23.x, b23.y};
#pragma unroll
            for (int rp = 0; rp < 2; rp++)
#pragma unroll
                for (int c = 0; c < 4; c++) fma2_(ppacc[rp][c], av[rp], bd[c]);
        }
        __syncthreads();

        // ===== Phase C1: PP store -> rows 0..49 =====
#pragma unroll
        for (int c = 0; c < 4; c++) {
            int o = n0 + c;
            if (o < HH) {
                float b = sbPP[o];
#pragma unroll
                for (int rp = 0; rp < 2; rp++) {
                    float2 f2 = unpk_(ppacc[rp][c]);
                    *(float2*)&CT[o * 68 + m0 + 2 * rp] =
                        make_float2(relu_(f2.x + b), relu_(f2.y + b));
                }
            }
        }
        __syncthreads();

        // ===== Phase C2: P4 + stage next tile =====
        {
            int tn2 = t + GRID_P;
            if (tn2 < NT) {
                int pn = tn2 * 64;
                for (int idx = tid; idx < 1024; idx += 256) {
                    int kk = idx & 15, p = idx >> 4;
                    pfT[kk * 68 + p] = (kk < FPR) ? __ldcs(&pf[(size_t)(pn + p) * FPR + kk]) : 0.0f;
                }
                if (tid < 128) sidx[tid] = atp[(size_t)pn * 2 + tid];
                if (tid < 65)  spsv[tid] = (tid == 0) ? -1 : split[pn + tid - 1];
            }
            ull acc2[2][4];
#pragma unroll
            for (int rp = 0; rp < 2; rp++)
#pragma unroll
                for (int c = 0; c < 4; c++) acc2[rp][c] = 0ull;
#pragma unroll 4
            for (int k = 0; k < 100; k++) {
                float4 b4 = *(const float4*)&WT[k * 52 + n0];
                ulonglong2 a2 = *(const ulonglong2*)&CT[k * 68 + m0];
                ull av[2] = {a2.x, a2.y};
                ull bd[4] = {dup_(b4.x), dup_(b4.y), dup_(b4.z), dup_(b4.w)};
#pragma unroll
                for (int rp = 0; rp < 2; rp++)
#pragma unroll
                    for (int c = 0; c < 4; c++) fma2_(acc2[rp][c], av[rp], bd[c]);
            }
            if (n0 < FO) {
                float accf[4][4];
#pragma unroll
                for (int rp = 0; rp < 2; rp++)
#pragma unroll
                    for (int c = 0; c < 4; c++) {
                        float2 f2 = unpk_(acc2[rp][c]);
                        accf[2 * rp][c] = f2.x;
                        accf[2 * rp + 1][c] = f2.y;
                    }
                float bb[4];
#pragma unroll
                for (int c = 0; c < 4; c++) bb[c] = sbP[n0 + c];
                bool full = (n0 + 3 < FO);
#pragma unroll
                for (int r = 0; r < 4; r++) {
                    size_t p = (size_t)(p0 + m0 + r);
                    float* dst = &outP[p * FO + n0];
                    __stcs((float2*)dst,
                           make_float2(relu_(accf[r][0] + bb[0]), relu_(accf[r][1] + bb[1])));
                    if (full)
                        __stcs((float2*)(dst + 2),
                               make_float2(relu_(accf[r][2] + bb[2]), relu_(accf[r][3] + bb[3])));
                }
            }
        }
        __syncthreads();
    }
}

// ============ K3: A-output (proven) ============
#define K3_SMEM_BYTES ((100*68*2 + 64) * 4)
__global__ __launch_bounds__(256) void atom_out_kernel(
    const float* __restrict__ W_A, const float* __restrict__ b_A,
    float* __restrict__ outA)
{
    extern __shared__ __align__(16) float sm3[];
    float* CcT = sm3;
    float* BsT = CcT + 100 * 68;
    float* bsh = BsT + 100 * 68;
    const int abase = blockIdx.x * 64;
    const int tid = threadIdx.x;

    for (int idx = tid; idx < 64 * 100; idx += 256) {
        int k = idx % 100, m = idx / 100;
        int a = abase + m;
        float v = 0.0f;
        if (a < NA) v = (k < HH) ? g_AA[a * HH + k] : g_PA[a * HH + (k - HH)];
        CcT[k * 68 + m] = v;
    }
    for (int idx = tid; idx < 64 * 100; idx += 256) {
        int k = idx % 100, o = idx / 100;
        BsT[k * 68 + o] = (o < FO) ? W_A[o * 2 * HH + k] : 0.0f;
    }
    if (tid < 64) bsh[tid] = (tid < FO) ? b_A[tid] : 0.0f;
    __syncthreads();

    const int tm = tid >> 4, tn = tid & 15;
    const int m0 = tm * 4, n0 = tn * 4;
    ull acc2[2][4];
#pragma unroll
    for (int rp = 0; rp < 2; rp++)
#pragma unroll
        for (int c = 0; c < 4; c++) acc2[rp][c] = 0ull;
#pragma unroll 4
    for (int k = 0; k < 100; k++) {
        ulonglong2 a2 = *(const ulonglong2*)&CcT[k * 68 + m0];
        float4 b4 = *(const float4*)&BsT[k * 68 + n0];
        ull av[2] = {a2.x, a2.y};
        ull bd[4] = {dup_(b4.x), dup_(b4.y), dup_(b4.z), dup_(b4.w)};
#pragma unroll
        for (int rp = 0; rp < 2; rp++)
#pragma unroll
            for (int c = 0; c < 4; c++) fma2_(acc2[rp][c], av[rp], bd[c]);
    }
#pragma unroll
    for (int rp = 0; rp < 2; rp++)
#pragma unroll
        for (int c = 0; c < 4; c++) {
            int o = n0 + c;
            if (o < FO) {
                float2 f2 = unpk_(acc2[rp][c]);
                int a0 = abase + m0 + 2 * rp;
                if (a0 < NA)     outA[(size_t)a0 * FO + o]       = relu_(f2.x + bsh[o]);
                if (a0 + 1 < NA) outA[(size_t)(a0 + 1) * FO + o] = relu_(f2.y + bsh[o]);
            }
        }
}

extern "C" void kernel_launch(void* const* d_in, const int* in_sizes, int n_in,
                              void* d_out, int out_size)
{
    const float* af    = (const float*)d_in[0];
    const float* pf    = (const float*)d_in[1];
    const int*   split = (const int*)  d_in[2];
    const int*   atp   = (const int*)  d_in[3];
    const float* W_AA  = (const float*)d_in[4];
    const float* b_AA  = (const float*)d_in[5];
    const float* W_PA  = (const float*)d_in[6];
    const float* b_PA  = (const float*)d_in[7];
    const float* W_A   = (const float*)d_in[8];
    const float* b_A   = (const float*)d_in[9];
    const float* W_AP  = (const float*)d_in[10];
    const float* b_AP  = (const float*)d_in[11];
    const float* W_PP  = (const float*)d_in[12];
    const float* b_PP  = (const float*)d_in[13];
    const float* W_P   = (const float*)d_in[14];
    const float* b_P   = (const float*)d_in[15];
    float* out = (float*)d_out;

    cudaFuncSetAttribute(pair_kernel, cudaFuncAttributeMaxDynamicSharedMemorySize, PAIR_SMEM_BYTES);
    cudaFuncSetAttribute(atom_out_kernel, cudaFuncAttributeMaxDynamicSharedMemorySize, K3_SMEM_BYTES);

    atom_pre_kernel<<<(NA + 63) / 64, 256>>>(af, W_AA, b_AA, W_AP);

    pair_kernel<<<GRID_P, 256, PAIR_SMEM_BYTES>>>(
        pf, split, atp, W_PA, b_PA, W_PP, b_PP, W_P, b_P, b_AP,
        out + (size_t)NA * FO);

    atom_out_kernel<<<(NA + 63) / 64, 256, K3_SMEM_BYTES>>>(W_A, b_A, out);
}

// round 16
// speedup vs baseline: 1.2212x; 1.2212x over previous
#include <cuda_runtime.h>

#define NA 100000
#define NP 3200000
#define FA 75
#define FPR 14
#define HH 50
#define FO 50
#define XS 52
typedef unsigned long long ull;

__device__ float g_AA[NA * HH];
__device__ float g_X1[NA * XS];
__device__ float g_X2[NA * XS];
__device__ float g_PA[NA * HH];

__device__ __forceinline__ float relu_(float x) { return fmaxf(x, 0.0f); }
__device__ __forceinline__ void fma2_(ull& d, ull a, ull b) {
    asm("fma.rn.f32x2 %0, %1, %2, %0;" : "+l"(d) : "l"(a), "l"(b));
}
__device__ __forceinline__ ull dup_(float x) {
    ull r; asm("mov.b64 %0, {%1, %1};" : "=l"(r) : "f"(x)); return r;
}
__device__ __forceinline__ float2 unpk_(ull v) {
    float2 f; asm("mov.b64 {%0, %1}, %2;" : "=f"(f.x), "=f"(f.y) : "l"(v)); return f;
}

// ============ K1: atom precompute (proven) ============
__global__ __launch_bounds__(256) void atom_pre_kernel(
    const float* __restrict__ af, const float* __restrict__ W_AA,
    const float* __restrict__ b_AA, const float* __restrict__ W_AP)
{
    __shared__ __align__(16) float AsT[76 * 68];
    __shared__ __align__(16) float BsT[76 * 68];
    __shared__ float bsh[64];
    const int abase = blockIdx.x * 64;
    const int tid = threadIdx.x;

    for (int idx = tid; idx < 64 * 76; idx += 256) {
        int k = idx % 76, m = idx / 76;
        int a = abase + m;
        AsT[k * 68 + m] = (k < FA && a < NA) ? af[a * FA + k] : 0.0f;
    }
    for (int idx = tid; idx < 64 * HH; idx += 256) {
        int m = idx / HH, o = idx % HH;
        int a = abase + m;
        if (a < NA) g_PA[a * HH + o] = 0.0f;
    }
    for (int idx = tid; idx < 64 * 2; idx += 256) {
        int m = idx >> 1, o = 50 + (idx & 1);
        int a = abase + m;
        if (a < NA) { g_X1[(size_t)a * XS + o] = 0.0f; g_X2[(size_t)a * XS + o] = 0.0f; }
    }
    if (tid < 64) bsh[tid] = (tid < HH) ? b_AA[tid] : 0.0f;

    const int tm = tid >> 4, tn = tid & 15;
    const int m0 = tm * 4, n0 = tn * 4;

    for (int mat = 0; mat < 3; mat++) {
        __syncthreads();
        const float* W; int ws, wo;
        if (mat == 0) { W = W_AA; ws = FA;     wo = 0; }
        else          { W = W_AP; ws = 2 * FA; wo = (mat == 1) ? 0 : FA; }
        for (int idx = tid; idx < 64 * 76; idx += 256) {
            int k = idx % 76, o = idx / 76;
            BsT[k * 68 + o] = (k < FA && o < HH) ? W[o * ws + wo + k] : 0.0f;
        }
        __syncthreads();
        ull acc2[2][4];
#pragma unroll
        for (int rp = 0; rp < 2; rp++)
#pragma unroll
            for (int c = 0; c < 4; c++) acc2[rp][c] = 0ull;
#pragma unroll 5
        for (int k = 0; k < 75; k++) {
            ulonglong2 a2 = *(const ulonglong2*)&AsT[k * 68 + m0];
            float4 b4 = *(const float4*)&BsT[k * 68 + n0];
            ull av[2] = {a2.x, a2.y};
            ull bd[4] = {dup_(b4.x), dup_(b4.y), dup_(b4.z), dup_(b4.w)};
#pragma unroll
            for (int rp = 0; rp < 2; rp++)
#pragma unroll
                for (int c = 0; c < 4; c++) fma2_(acc2[rp][c], av[rp], bd[c]);
        }
        float* dst = (mat == 0) ? g_AA : ((mat == 1) ? g_X1 : g_X2);
        const int ds = (mat == 0) ? HH : XS;
#pragma unroll
        for (int rp = 0; rp < 2; rp++)
#pragma unroll
            for (int c = 0; c < 4; c++) {
                int o = n0 + c;
                if (o < HH) {
                    float2 f2 = unpk_(acc2[rp][c]);
                    int a0 = abase + m0 + 2 * rp;
                    if (mat == 0) { f2.x = relu_(f2.x + bsh[o]); f2.y = relu_(f2.y + bsh[o]); }
                    if (a0 < NA)     dst[(size_t)a0 * ds + o]       = f2.x;
                    if (a0 + 1 < NA) dst[(size_t)(a0 + 1) * ds + o] = f2.y;
                }
            }
    }
}

// ============ K2: persistent pair kernel, fused phases, ballot segsum (R13 champion) ============
#define NT (NP / 64)
#define GRID_P 444
#define PAIR_SMEM_BYTES (17336 * 4)

__global__ __launch_bounds__(256, 3) void pair_kernel(
    const float* __restrict__ pf, const int* __restrict__ split,
    const int* __restrict__ atp,
    const float* __restrict__ W_PA, const float* __restrict__ b_PA,
    const float* __restrict__ W_PP, const float* __restrict__ b_PP,
    const float* __restrict__ W_P,  const float* __restrict__ b_P,
    const float* __restrict__ b_AP, float* __restrict__ outP)
{
    extern __shared__ __align__(16) float sm[];
    float* CT   = sm;              // [100][68]
    float* WT   = CT + 6800;       // [100][68]  (row-remapped W_P^T)
    float* pfT  = WT + 6800;       // [16][68]
    float* WpaT = pfT + 1088;      // [16][68]
    float* WppT = WpaT + 1088;     // [16][68]
    float* sbAP = WppT + 1088;     // 52
    float* sbPP = sbAP + 52;
    float* sbPA = sbPP + 52;
    float* sbP  = sbPA + 52;
    int* sidx   = (int*)(sbP + 52);   // 128
    int* spsv   = sidx + 128;         // 68
    int* sbal   = spsv + 68;          // 2

    const int tid = threadIdx.x;
    const int tm = tid >> 4, tn = tid & 15;
    const int m0 = tm * 4, n0 = tn * 4;

    // one-time weight staging (WT rows remapped: PP part rows 0..49, S part 50..99)
    for (int idx = tid; idx < 6400; idx += 256) {
        int r = idx % 100, o = idx / 100;
        int kk = (r < 50) ? (r + 50) : (r - 50);
        WT[r * 68 + o] = (o < FO) ? W_P[o * 2 * HH + kk] : 0.0f;
    }
    for (int idx = tid; idx < 1024; idx += 256) {
        int k = idx & 15, o = idx >> 4;
        bool v = (k < FPR && o < HH);
        WpaT[k * 68 + o] = v ? W_PA[o * FPR + k] : 0.0f;
        WppT[k * 68 + o] = v ? W_PP[o * FPR + k] : 0.0f;
    }
    if (tid < 52) {
        sbAP[tid] = (tid < HH) ? b_AP[tid] : 0.0f;
        sbPP[tid] = (tid < HH) ? b_PP[tid] : 0.0f;
        sbPA[tid] = (tid < HH) ? b_PA[tid] : 0.0f;
        sbP[tid]  = (tid < FO) ? b_P[tid]  : 0.0f;
    }
    {
        int t0 = blockIdx.x;
        if (t0 < NT) {
            int p0 = t0 * 64;
            for (int idx = tid; idx < 1024; idx += 256) {
                int kk = idx & 15, p = idx >> 4;
                pfT[kk * 68 + p] = (kk < FPR) ? __ldcs(&pf[(size_t)(p0 + p) * FPR + kk]) : 0.0f;
            }
            if (tid < 128) sidx[tid] = atp[(size_t)p0 * 2 + tid];
            if (tid < 65)  spsv[tid] = (tid == 0) ? -1 : split[p0 + tid - 1];
        }
    }
    __syncthreads();

    for (int t = blockIdx.x; t < NT; t += GRID_P) {
        const int p0 = t * 64;

        // ======== Phase A: ballot head-detect + S gathers -> rows 50..99 + P1 -> rows 0..49 ========
        if (tid < 64) {
            bool ish = (spsv[tid + 1] != spsv[tid]);   // forced head at tid=0 (spsv[0]=-1)
            unsigned bm = __ballot_sync(0xffffffffu, ish);
            if ((tid & 31) == 0) sbal[tid >> 5] = (int)bm;
        }
        for (int idx = tid; idx < 64 * 13; idx += 256) {
            int p = idx / 13, c = idx % 13;
            int k0 = c * 4;
            int i = sidx[2 * p], j = sidx[2 * p + 1];
            float4 a = *(const float4*)(g_X1 + (size_t)i * XS + k0);
            float4 b = *(const float4*)(g_X2 + (size_t)j * XS + k0);
            float4 d = *(const float4*)(g_X1 + (size_t)j * XS + k0);
            float4 e = *(const float4*)(g_X2 + (size_t)i * XS + k0);
            float4 bi = *(const float4*)(sbAP + k0);
            CT[(50 + k0 + 0) * 68 + p] = relu_(a.x + b.x + bi.x) + relu_(d.x + e.x + bi.x);
            CT[(50 + k0 + 1) * 68 + p] = relu_(a.y + b.y + bi.y) + relu_(d.y + e.y + bi.y);
            if (c < 12) {
                CT[(50 + k0 + 2) * 68 + p] = relu_(a.z + b.z + bi.z) + relu_(d.z + e.z + bi.z);
                CT[(50 + k0 + 3) * 68 + p] = relu_(a.w + b.w + bi.w) + relu_(d.w + e.w + bi.w);
            }
        }
        {   // P1: PA -> rows 0..49
            ull acc2[2][4];
#pragma unroll
            for (int rp = 0; rp < 2; rp++)
#pragma unroll
                for (int c = 0; c < 4; c++) acc2[rp][c] = 0ull;
#pragma unroll
            for (int k = 0; k < FPR; k++) {
                float4 b4 = *(const float4*)&WpaT[k * 68 + n0];
                ulonglong2 a2 = *(const ulonglong2*)&pfT[k * 68 + m0];
                ull av[2] = {a2.x, a2.y};
                ull bd[4] = {dup_(b4.x), dup_(b4.y), dup_(b4.z), dup_(b4.w)};
#pragma unroll
                for (int rp = 0; rp < 2; rp++)
#pragma unroll
                    for (int c = 0; c < 4; c++) fma2_(acc2[rp][c], av[rp], bd[c]);
            }
#pragma unroll
            for (int c = 0; c < 4; c++) {
                int o = n0 + c;
                if (o < HH) {
                    float b = sbPA[o];
#pragma unroll
                    for (int rp = 0; rp < 2; rp++) {
                        float2 f2 = unpk_(acc2[rp][c]);
                        *(float2*)&CT[o * 68 + m0 + 2 * rp] =
                            make_float2(relu_(f2.x + b), relu_(f2.y + b));
                    }
                }
            }
        }
        __syncthreads();

        // ======== Phase B: segsum (ballot-derived bounds, vectorized) + PP -> regs ========
        ull ppacc[2][4];
#pragma unroll
        for (int rp = 0; rp < 2; rp++)
#pragma unroll
            for (int c = 0; c < 4; c++) ppacc[rp][c] = 0ull;
        {
            ull mask = (ull)(unsigned)sbal[0] | ((ull)(unsigned)sbal[1] << 32);
            int nh = __popcll(mask);
            for (int w = tid; w < nh * 64; w += 256) {
                int o = w & 63, hi = w >> 6;
                if (o < HH) {
                    ull mm = mask;
                    for (int it = 0; it < hi; it++) mm &= mm - 1;
                    int h = __ffsll((long long)mm) - 1;
                    int e;
                    if (h >= 63) e = 64;
                    else {
                        ull rest = mask >> (h + 1);
                        e = rest ? (h + 1 + __ffsll((long long)rest) - 1) : 64;
                    }
                    int seg = spsv[h + 1];
                    const float* cr = &CT[o * 68];
                    float s = 0.0f;
                    int q = h;
                    int e4 = h + ((e - h) & ~3);
                    for (; q < e4; q += 4)
                        s += (cr[q] + cr[q + 1]) + (cr[q + 2] + cr[q + 3]);
                    for (; q < e; q++) s += cr[q];
                    atomicAdd(&g_PA[(size_t)seg * HH + o], s);
                }
            }
        }
#pragma unroll
        for (int k = 0; k < FPR; k++) {
            float4 b4 = *(const float4*)&WppT[k * 68 + n0];
            ulonglong2 a2 = *(const ulonglong2*)&pfT[k * 68 + m0];
            ull av[2] = {a2.x, a2.y};
            ull bd[4] = {dup_(b4.x), dup_(b4.y), dup_(b4.z), dup_(b4.w)};
#pragma unroll
            for (int rp = 0; rp < 2; rp++)
#pragma unroll
                for (int c = 0; c < 4; c++) fma2_(ppacc[rp][c], av[rp], bd[c]);
        }
        __syncthreads();

        // ======== Phase C1: PP store -> rows 0..49 ========
#pragma unroll
        for (int c = 0; c < 4; c++) {
            int o = n0 + c;
            if (o < HH) {
                float b = sbPP[o];
#pragma unroll
                for (int rp = 0; rp < 2; rp++) {
                    float2 f2 = unpk_(ppacc[rp][c]);
                    *(float2*)&CT[o * 68 + m0 + 2 * rp] =
                        make_float2(relu_(f2.x + b), relu_(f2.y + b));
                }
            }
        }
        __syncthreads();

        // ======== Phase C2: P4 + stage next tile ========
        {
            int tn2 = t + GRID_P;
            if (tn2 < NT) {
                int pn = tn2 * 64;
                for (int idx = tid; idx < 1024; idx += 256) {
                    int kk = idx & 15, p = idx >> 4;
                    pfT[kk * 68 + p] = (kk < FPR) ? __ldcs(&pf[(size_t)(pn + p) * FPR + kk]) : 0.0f;
                }
                if (tid < 128) sidx[tid] = atp[(size_t)pn * 2 + tid];
                if (tid < 65)  spsv[tid] = (tid == 0) ? -1 : split[pn + tid - 1];
            }
            ull acc2[2][4];
#pragma unroll
            for (int rp = 0; rp < 2; rp++)
#pragma unroll
                for (int c = 0; c < 4; c++) acc2[rp][c] = 0ull;
#pragma unroll 4
            for (int k = 0; k < 100; k++) {
                float4 b4 = *(const float4*)&WT[k * 68 + n0];
                ulonglong2 a2 = *(const ulonglong2*)&CT[k * 68 + m0];
                ull av[2] = {a2.x, a2.y};
                ull bd[4] = {dup_(b4.x), dup_(b4.y), dup_(b4.z), dup_(b4.w)};
#pragma unroll
                for (int rp = 0; rp < 2; rp++)
#pragma unroll
                    for (int c = 0; c < 4; c++) fma2_(acc2[rp][c], av[rp], bd[c]);
            }
            if (n0 < FO) {
                float accf[4][4];
#pragma unroll
                for (int rp = 0; rp < 2; rp++)
#pragma unroll
                    for (int c = 0; c < 4; c++) {
                        float2 f2 = unpk_(acc2[rp][c]);
                        accf[2 * rp][c] = f2.x;
                        accf[2 * rp + 1][c] = f2.y;
                    }
                float bb[4];
#pragma unroll
                for (int c = 0; c < 4; c++) bb[c] = sbP[n0 + c];
                bool full = (n0 + 3 < FO);
#pragma unroll
                for (int r = 0; r < 4; r++) {
                    size_t p = (size_t)(p0 + m0 + r);
                    float* dst = &outP[p * FO + n0];
                    __stcs((float2*)dst,
                           make_float2(relu_(accf[r][0] + bb[0]), relu_(accf[r][1] + bb[1])));
                    if (full)
                        __stcs((float2*)(dst + 2),
                               make_float2(relu_(accf[r][2] + bb[2]), relu_(accf[r][3] + bb[3])));
                }
            }
        }
        __syncthreads();
    }
}

// ============ K3: A-output (proven) ============
#define K3_SMEM_BYTES ((100*68*2 + 64) * 4)
__global__ __launch_bounds__(256) void atom_out_kernel(
    const float* __restrict__ W_A, const float* __restrict__ b_A,
    float* __restrict__ outA)
{
    extern __shared__ __align__(16) float sm3[];
    float* CcT = sm3;
    float* BsT = CcT + 100 * 68;
    float* bsh = BsT + 100 * 68;
    const int abase = blockIdx.x * 64;
    const int tid = threadIdx.x;

    for (int idx = tid; idx < 64 * 100; idx += 256) {
        int k = idx % 100, m = idx / 100;
        int a = abase + m;
        float v = 0.0f;
        if (a < NA) v = (k < HH) ? g_AA[a * HH + k] : g_PA[a * HH + (k - HH)];
        CcT[k * 68 + m] = v;
    }
    for (int idx = tid; idx < 64 * 100; idx += 256) {
        int k = idx % 100, o = idx / 100;
        BsT[k * 68 + o] = (o < FO) ? W_A[o * 2 * HH + k] : 0.0f;
    }
    if (tid < 64) bsh[tid] = (tid < FO) ? b_A[tid] : 0.0f;
    __syncthreads();

    const int tm = tid >> 4, tn = tid & 15;
    const int m0 = tm * 4, n0 = tn * 4;
    ull acc2[2][4];
#pragma unroll
    for (int rp = 0; rp < 2; rp++)
#pragma unroll
        for (int c = 0; c < 4; c++) acc2[rp][c] = 0ull;
#pragma unroll 4
    for (int k = 0; k < 100; k++) {
        ulonglong2 a2 = *(const ulonglong2*)&CcT[k * 68 + m0];
        float4 b4 = *(const float4*)&BsT[k * 68 + n0];
        ull av[2] = {a2.x, a2.y};
        ull bd[4] = {dup_(b4.x), dup_(b4.y), dup_(b4.z), dup_(b4.w)};
#pragma unroll
        for (int rp = 0; rp < 2; rp++)
#pragma unroll
            for (int c = 0; c < 4; c++) fma2_(acc2[rp][c], av[rp], bd[c]);
    }
#pragma unroll
    for (int rp = 0; rp < 2; rp++)
#pragma unroll
        for (int c = 0; c < 4; c++) {
            int o = n0 + c;
            if (o < FO) {
                float2 f2 = unpk_(acc2[rp][c]);
                int a0 = abase + m0 + 2 * rp;
                if (a0 < NA)     outA[(size_t)a0 * FO + o]       = relu_(f2.x + bsh[o]);
                if (a0 + 1 < NA) outA[(size_t)(a0 + 1) * FO + o] = relu_(f2.y + bsh[o]);
            }
        }
}

extern "C" void kernel_launch(void* const* d_in, const int* in_sizes, int n_in,
                              void* d_out, int out_size)
{
    const float* af    = (const float*)d_in[0];
    const float* pf    = (const float*)d_in[1];
    const int*   split = (const int*)  d_in[2];
    const int*   atp   = (const int*)  d_in[3];
    const float* W_AA  = (const float*)d_in[4];
    const float* b_AA  = (const float*)d_in[5];
    const float* W_PA  = (const float*)d_in[6];
    const float* b_PA  = (const float*)d_in[7];
    const float* W_A   = (const float*)d_in[8];
    const float* b_A   = (const float*)d_in[9];
    const float* W_AP  = (const float*)d_in[10];
    const float* b_AP  = (const float*)d_in[11];
    const float* W_PP  = (const float*)d_in[12];
    const float* b_PP  = (const float*)d_in[13];
    const float* W_P   = (const float*)d_in[14];
    const float* b_P   = (const float*)d_in[15];
    float* out = (float*)d_out;

    cudaFuncSetAttribute(pair_kernel, cudaFuncAttributeMaxDynamicSharedMemorySize, PAIR_SMEM_BYTES);
    cudaFuncSetAttribute(atom_out_kernel, cudaFuncAttributeMaxDynamicSharedMemorySize, K3_SMEM_BYTES);

    atom_pre_kernel<<<(NA + 63) / 64, 256>>>(af, W_AA, b_AA, W_AP);

    pair_kernel<<<GRID_P, 256, PAIR_SMEM_BYTES>>>(
        pf, split, atp, W_PA, b_PA, W_PP, b_PP, W_P, b_P, b_AP,
        out + (size_t)NA * FO);

    atom_out_kernel<<<(NA + 63) / 64, 256, K3_SMEM_BYTES>>>(W_A, b_A, out);
}